// round 6
// baseline (speedup 1.0000x reference)
#include <cuda_runtime.h>

#define HID 64
typedef unsigned long long u64;

__device__ __forceinline__ u64 pk2(float lo, float hi) {
    u64 r; asm("mov.b64 %0, {%1,%2};" : "=l"(r) : "f"(lo), "f"(hi)); return r;
}
__device__ __forceinline__ void upk2(u64 v, float& lo, float& hi) {
    asm("mov.b64 {%0,%1}, %2;" : "=f"(lo), "=f"(hi) : "l"(v));
}
__device__ __forceinline__ u64 ffma2(u64 a, u64 b, u64 c) {
    u64 d; asm("fma.rn.f32x2 %0, %1, %2, %3;" : "=l"(d) : "l"(a), "l"(b), "l"(c)); return d;
}

__global__ void zero_kernel(float* __restrict__ out, int n) {
    int i = blockIdx.x * blockDim.x + threadIdx.x;
    if (i < n) out[i] = 0.0f;
}

// h-PAIR packed scheme, one kernel per family (per-family register allocation).
// Weight block per h2 (stride NW = DIN+1+9 u64):
//   [0,DIN)    : (W1[s,2h2], W1[s,2h2+1])
//   DIN        : (b1[2h2], b1[2h2+1])
//   (DIN,NW)   : (W2[2h2,m], W2[2h2+1,m])
// Loaded as LDS.64, W2 pairs loaded JUST-IN-TIME before their EPT uses so the
// live weight-register window stays ~4 u64 (vs 14 staged) — keeps regs low.
template<int DIN, int EPT>
__global__ __launch_bounds__(128)
void family_kernel(
    const float* __restrict__ x,
    const int*   __restrict__ edges,
    const float* __restrict__ attr,
    const float* __restrict__ W1, const float* __restrict__ b1,
    const float* __restrict__ W2, const float* __restrict__ b2,
    float* __restrict__ out, int E)
{
    constexpr int NW = DIN + 1 + 9;          // u64 per h2 block
    __shared__ __align__(16) u64 sWB[NW * 32];
    __shared__ __align__(16) u64 sB2[9];

    for (int idx = threadIdx.x; idx < NW * 32; idx += blockDim.x) {
        int h2 = idx / NW, s = idx - h2 * NW;
        int h0 = 2 * h2, h1 = 2 * h2 + 1;
        float lo, hi;
        if (s < DIN)       { lo = W1[s * HID + h0]; hi = W1[s * HID + h1]; }
        else if (s == DIN) { lo = b1[h0];           hi = b1[h1]; }
        else               { int m = s - DIN - 1; lo = W2[h0 * 9 + m]; hi = W2[h1 * 9 + m]; }
        sWB[idx] = pk2(lo, hi);
    }
    if (threadIdx.x < 9) sB2[threadIdx.x] = pk2(b2[threadIdx.x], 0.0f);
    __syncthreads();

    const int tid    = blockIdx.x * blockDim.x + threadIdx.x;
    const int stride = gridDim.x * blockDim.x;

    u64  dd[EPT][DIN];     // (d,d) duplicated MLP inputs
    u64  acc[EPT][9];      // packed accumulators (even-h lane0, odd-h lane1)
    int  tgt[EPT];
    bool valid[EPT];

    #pragma unroll
    for (int k = 0; k < EPT; k++) {
        int e = tid + k * stride;
        valid[k] = (e < E);
        int ee = valid[k] ? e : 0;
        float dv[DIN];
        int i;
        if (DIN == 3) {
            int j = edges[ee];
            i = edges[E + ee];
            dv[0] = x[3*j+0] - x[3*i+0];
            dv[1] = x[3*j+1] - x[3*i+1];
            dv[2] = x[3*j+2] - x[3*i+2];
        } else {
            int j  = edges[ee];
            int kk = edges[E + ee];
            i = edges[2*E + ee];
            float xk0 = x[3*kk+0], xk1 = x[3*kk+1], xk2 = x[3*kk+2];
            dv[0] = xk0 - x[3*j+0];
            dv[1] = xk1 - x[3*j+1];
            dv[2] = xk2 - x[3*j+2];
            dv[3] = x[3*i+0] - xk0;
            dv[4] = x[3*i+1] - xk1;
            dv[5] = x[3*i+2] - xk2;
        }
        tgt[k] = i;
        #pragma unroll
        for (int q = 0; q < DIN; q++) dd[k][q] = pk2(dv[q], dv[q]);
        #pragma unroll
        for (int m = 0; m < 9; m++) acc[k][m] = sB2[m];
    }

    // Mainloop: 32 h-pair iterations. Layer-1 weights loaded upfront (small),
    // W2 pairs loaded just-in-time per output column.
    #pragma unroll 2
    for (int h2 = 0; h2 < 32; h2++) {
        const u64* wp = sWB + h2 * NW;

        u64 w1p[DIN];
        #pragma unroll
        for (int i = 0; i < DIN; i++) w1p[i] = wp[i];
        u64 bh = wp[DIN];

        u64 hv[EPT];
        #pragma unroll
        for (int k = 0; k < EPT; k++) {
            u64 t = bh;
            #pragma unroll
            for (int i = 0; i < DIN; i++) t = ffma2(dd[k][i], w1p[i], t);
            float lo, hi; upk2(t, lo, hi);
            lo = fmaxf(lo, 0.0f); hi = fmaxf(hi, 0.0f);
            hv[k] = pk2(lo, hi);
        }

        #pragma unroll
        for (int m = 0; m < 9; m++) {
            u64 w = wp[DIN + 1 + m];        // JIT load: short live range
            #pragma unroll
            for (int k = 0; k < EPT; k++)
                acc[k][m] = ffma2(hv[k], w, acc[k][m]);
        }
    }

    // Epilogue: merge h-lanes, matvec with attr, scatter-add.
    #pragma unroll
    for (int k = 0; k < EPT; k++) {
        if (!valid[k]) continue;
        int e = tid + k * stride;
        float a0 = attr[3*e+0], a1 = attr[3*e+1], a2v = attr[3*e+2];
        #pragma unroll
        for (int i = 0; i < 3; i++) {
            float m0lo, m0hi, m1lo, m1hi, m2lo, m2hi;
            upk2(acc[k][3*i+0], m0lo, m0hi);
            upk2(acc[k][3*i+1], m1lo, m1hi);
            upk2(acc[k][3*i+2], m2lo, m2hi);
            float y = fmaf(m0lo + m0hi, a0,
                      fmaf(m1lo + m1hi, a1,
                           (m2lo + m2hi) * a2v));
            atomicAdd(&out[3*tgt[k] + i], y);
        }
    }
}

#define EPT3B 4   // DIN=3 families
#define EPT6B 2   // DIN=6 family (register budget -> occupancy)

extern "C" void kernel_launch(void* const* d_in, const int* in_sizes, int n_in,
                              void* d_out, int out_size)
{
    const float* x   = (const float*)d_in[0];
    const int*   e2  = (const int*)  d_in[1];
    const int*   e3  = (const int*)  d_in[2];
    const int*   es  = (const int*)  d_in[3];
    const float* a2  = (const float*)d_in[5];
    const float* a3  = (const float*)d_in[6];
    const float* as  = (const float*)d_in[7];
    const float* W1_2b = (const float*)d_in[9];
    const float* b1_2b = (const float*)d_in[10];
    const float* W2_2b = (const float*)d_in[11];
    const float* b2_2b = (const float*)d_in[12];
    const float* W1_3b = (const float*)d_in[13];
    const float* b1_3b = (const float*)d_in[14];
    const float* W2_3b = (const float*)d_in[15];
    const float* b2_3b = (const float*)d_in[16];
    const float* W1_s  = (const float*)d_in[17];
    const float* b1_s  = (const float*)d_in[18];
    const float* W2_s  = (const float*)d_in[19];
    const float* b2_s  = (const float*)d_in[20];

    const int E2 = in_sizes[1] / 2;
    const int E3 = in_sizes[2] / 3;
    const int ES = in_sizes[3] / 2;

    float* out = (float*)d_out;

    zero_kernel<<<(out_size + 255) / 256, 256>>>(out, out_size);

    constexpr int BLK = 128;
    const int B2 = (E2 + EPT3B * BLK - 1) / (EPT3B * BLK);
    const int B3 = (E3 + EPT6B * BLK - 1) / (EPT6B * BLK);
    const int BS = (ES + EPT3B * BLK - 1) / (EPT3B * BLK);

    family_kernel<3, EPT3B><<<B2, BLK>>>(x, e2, a2, W1_2b, b1_2b, W2_2b, b2_2b, out, E2);
    family_kernel<6, EPT6B><<<B3, BLK>>>(x, e3, a3, W1_3b, b1_3b, W2_3b, b2_3b, out, E3);
    family_kernel<3, EPT3B><<<BS, BLK>>>(x, es, as, W1_s, b1_s, W2_s, b2_s, out, ES);
}